// round 3
// baseline (speedup 1.0000x reference)
#include <cuda_runtime.h>
#include <math.h>

// Problem constants (fixed by the reference)
#define NB 2
#define NN 5000
#define NE 160000
#define F_INN 128
#define HID 128
#define ED 16
#define IN_EDGE 288   // 2*128 + 16 + 16
#define TILE_E 64
#define TILE_N 64
#define NTHREADS 256

// Scratch (allocation-free rule -> __device__ globals)
__device__ float g_agg_h[NB * NN * HID];   // 5.12 MB
__device__ float g_agg_c[NB * NN * 12];    // 480 KB
__device__ float g_cnt[NN];                // 20 KB

__device__ __forceinline__ void red_add_v4(float* p, float a, float b, float c, float d) {
    asm volatile("red.global.add.v4.f32 [%0], {%1,%2,%3,%4};"
                 :: "l"(p), "f"(a), "f"(b), "f"(c), "f"(d) : "memory");
}

__global__ void zero_kernel() {
    int stride = gridDim.x * blockDim.x;
    int i = blockIdx.x * blockDim.x + threadIdx.x;
    for (int idx = i; idx < NB * NN * HID; idx += stride) g_agg_h[idx] = 0.f;
    for (int idx = i; idx < NB * NN * 12;  idx += stride) g_agg_c[idx] = 0.f;
    for (int idx = i; idx < NN;            idx += stride) g_cnt[idx]   = 0.f;
}

// Register-blocked tile GEMM: C[64 rows][128 out] += A(smem, [K][65] transposed) * W([K][128] global).
// Thread (warp wp, lane) owns rows eb..eb+7 (eb = wp*8) and outputs lane*4..lane*4+3.
// A-loads are warp-uniform (broadcast, conflict-free); W-loads are L1-resident LDG.128.
__device__ __forceinline__ void gemm_tile(const float* __restrict__ A,
                                          const float* __restrict__ W,
                                          int K, int eb, int lane,
                                          float acc[8][4]) {
#pragma unroll
    for (int ee = 0; ee < 8; ee++)
#pragma unroll
        for (int j = 0; j < 4; j++) acc[ee][j] = 0.f;
    const float4* W4 = (const float4*)W;
#pragma unroll 2
    for (int k = 0; k < K; k++) {
        float4 w = __ldg(&W4[k * 32 + lane]);
        const float* a = A + k * 65 + eb;
#pragma unroll
        for (int ee = 0; ee < 8; ee++) {
            float av = a[ee];
            acc[ee][0] = fmaf(av, w.x, acc[ee][0]);
            acc[ee][1] = fmaf(av, w.y, acc[ee][1]);
            acc[ee][2] = fmaf(av, w.z, acc[ee][2]);
            acc[ee][3] = fmaf(av, w.w, acc[ee][3]);
        }
    }
}

__device__ __forceinline__ void store_relu(float* __restrict__ S,
                                           const float* __restrict__ bias,
                                           int eb, int lane, const float acc[8][4]) {
    float4 bb = __ldg((const float4*)bias + lane);
#pragma unroll
    for (int ee = 0; ee < 8; ee++) {
        int e = eb + ee;
        S[(lane * 4 + 0) * 65 + e] = fmaxf(acc[ee][0] + bb.x, 0.f);
        S[(lane * 4 + 1) * 65 + e] = fmaxf(acc[ee][1] + bb.y, 0.f);
        S[(lane * 4 + 2) * 65 + e] = fmaxf(acc[ee][2] + bb.z, 0.f);
        S[(lane * 4 + 3) * 65 + e] = fmaxf(acc[ee][3] + bb.w, 0.f);
    }
}

// SMEM (floats): XS[288][65] | EFS[128][65] | CDS[64][12] | NRM[64] | ROWS[64] COLS[64] (ints)
#define EDGE_SMEM_FLOATS (IN_EDGE * 65 + HID * 65 + TILE_E * 12 + TILE_E + TILE_E)
#define EDGE_SMEM_BYTES  (EDGE_SMEM_FLOATS * 4 + TILE_E * 4)

__global__ void __launch_bounds__(NTHREADS, 2)
edge_kernel(const float* __restrict__ h, const float* __restrict__ coord,
            const int* __restrict__ ei, const float* __restrict__ ea,
            const float* __restrict__ W1, const float* __restrict__ b1,
            const float* __restrict__ W2, const float* __restrict__ b2,
            const float* __restrict__ Wc1, const float* __restrict__ bc1,
            const float* __restrict__ Wc2) {
    const int b   = blockIdx.y;
    const int e0  = blockIdx.x * TILE_E;
    const int tid = threadIdx.x;
    const int lane = tid & 31;
    const int wp   = tid >> 5;
    const int eb   = wp * 8;

    extern __shared__ float sm[];
    float* XS  = sm;                       // [288][65]
    float* EFS = XS + IN_EDGE * 65;        // [128][65]
    float* CDS = EFS + HID * 65;           // [64][12]
    float* NRM = CDS + TILE_E * 12;        // [64]
    int*   ROWS = (int*)(NRM + TILE_E);
    int*   COLS = ROWS + TILE_E;

    const float* hb = h + (size_t)b * NN * F_INN;
    const float* cb = coord + (size_t)b * NN * 12;

    if (tid < TILE_E) {
        ROWS[tid] = ei[e0 + tid];
        COLS[tid] = ei[NE + e0 + tid];
    }
    __syncthreads();

    // Gather h[row] (k: 0..127) and h[col] (k: 128..255) into XS (transposed, conflict-free writes)
    for (int idx = tid; idx < TILE_E * F_INN; idx += NTHREADS) {
        int e = idx >> 7, k = idx & 127;
        XS[k * 65 + e] = hb[ROWS[e] * F_INN + k];
    }
    for (int idx = tid; idx < TILE_E * F_INN; idx += NTHREADS) {
        int e = idx >> 7, k = idx & 127;
        XS[(128 + k) * 65 + e] = hb[COLS[e] * F_INN + k];
    }
    // cd = coord[row] - coord[col]  ([4][3] per edge)
    for (int idx = tid; idx < TILE_E * 12; idx += NTHREADS) {
        int e = idx / 12, c = idx % 12;
        CDS[e * 12 + c] = cb[ROWS[e] * 12 + c] - cb[COLS[e] * 12 + c];
    }
    // edge_attr (k: 272..287)
    for (int idx = tid; idx < TILE_E * ED; idx += NTHREADS) {
        int e = idx >> 4, c = idx & 15;
        XS[(272 + c) * 65 + e] = ea[(size_t)(e0 + e) * ED + c];
    }
    __syncthreads();

    // prod[jk] = dot(cd[j], cd[k2]) (unnormalized, k: 256..271)
    for (int idx = tid; idx < TILE_E * 16; idx += NTHREADS) {
        int e = idx >> 4, jk = idx & 15;
        int j = jk >> 2, k2 = jk & 3;
        const float* cde = CDS + e * 12;
        float p = cde[j * 3] * cde[k2 * 3] + cde[j * 3 + 1] * cde[k2 * 3 + 1] +
                  cde[j * 3 + 2] * cde[k2 * 3 + 2];
        XS[(256 + jk) * 65 + e] = p;
    }
    __syncthreads();
    if (tid < TILE_E) {
        float s = 0.f;
#pragma unroll
        for (int jk = 0; jk < 16; jk++) { float p = XS[(256 + jk) * 65 + tid]; s += p * p; }
        NRM[tid] = 1.0f / fmaxf(sqrtf(s), 1e-12f);
    }
    __syncthreads();
    for (int idx = tid; idx < TILE_E * 16; idx += NTHREADS) {
        int e = idx >> 4, jk = idx & 15;
        XS[(256 + jk) * 65 + e] *= NRM[e];
    }
    __syncthreads();

    float acc[8][4];

    // edge_mlp layer 1: [64,288] @ [288,128] -> relu -> EFS
    gemm_tile(XS, W1, IN_EDGE, eb, lane, acc);
    store_relu(EFS, b1, eb, lane, acc);
    __syncthreads();

    // edge_mlp layer 2: [64,128] @ [128,128] -> relu -> ef (regs)
    gemm_tile(EFS, W2, HID, eb, lane, acc);
    float ef[8][4];
    {
        float4 bb = __ldg((const float4*)b2 + lane);
#pragma unroll
        for (int ee = 0; ee < 8; ee++) {
            ef[ee][0] = fmaxf(acc[ee][0] + bb.x, 0.f);
            ef[ee][1] = fmaxf(acc[ee][1] + bb.y, 0.f);
            ef[ee][2] = fmaxf(acc[ee][2] + bb.z, 0.f);
            ef[ee][3] = fmaxf(acc[ee][3] + bb.w, 0.f);
        }
    }
    // scatter ef into agg_h: all 32 lanes of a warp hit one node's 128
    // consecutive floats -> one coalesced 512B vector reduction per (warp, edge)
#pragma unroll
    for (int ee = 0; ee < 8; ee++) {
        int r = ROWS[eb + ee];
        float* p = g_agg_h + ((size_t)b * NN + r) * HID + lane * 4;
        red_add_v4(p, ef[ee][0], ef[ee][1], ef[ee][2], ef[ee][3]);
    }
    __syncthreads();   // all GEMM2 reads of EFS done
    // overwrite EFS with ef for coord_mlp input
#pragma unroll
    for (int ee = 0; ee < 8; ee++) {
        int e = eb + ee;
        EFS[(lane * 4 + 0) * 65 + e] = ef[ee][0];
        EFS[(lane * 4 + 1) * 65 + e] = ef[ee][1];
        EFS[(lane * 4 + 2) * 65 + e] = ef[ee][2];
        EFS[(lane * 4 + 3) * 65 + e] = ef[ee][3];
    }
    __syncthreads();

    // coord_mlp layer 1: relu(ef @ Wc1 + bc1)
    gemm_tile(EFS, Wc1, HID, eb, lane, acc);
    __syncthreads();   // all reads of ef done before overwrite
    store_relu(EFS, bc1, eb, lane, acc);
    __syncthreads();

    // coord_mlp layer 2: [64,128] @ [128,4]; one thread per (edge, m)
    {
        int e = tid >> 2, m = tid & 3;
        float s = 0.f;
#pragma unroll 4
        for (int j = 0; j < 128; j++) s += EFS[j * 65 + e] * __ldg(&Wc2[j * 4 + m]);
        int r = ROWS[e];
        float* p = g_agg_c + ((size_t)b * NN + r) * 12 + m * 3;
        const float* cde = CDS + e * 12 + m * 3;
        atomicAdd(p + 0, cde[0] * s);
        atomicAdd(p + 1, cde[1] * s);
        atomicAdd(p + 2, cde[2] * s);
    }
    // per-node edge counts (batch-independent; count once)
    if (b == 0 && tid < TILE_E) atomicAdd(&g_cnt[ROWS[tid]], 1.0f);
}

// SMEM (floats): ZS[256][65] | CS[128][65]
#define NODE_SMEM_BYTES ((256 * 65 + 128 * 65) * 4)

__global__ void __launch_bounds__(NTHREADS, 2)
node_kernel(const float* __restrict__ h, const float* __restrict__ coord,
            const float* __restrict__ Wn1, const float* __restrict__ bn1,
            const float* __restrict__ Wn2, const float* __restrict__ bn2,
            float* __restrict__ out_h, float* __restrict__ out_c) {
    const int b   = blockIdx.y;
    const int n0  = blockIdx.x * TILE_N;
    const int tid = threadIdx.x;
    const int lane = tid & 31;
    const int wp   = tid >> 5;
    const int eb   = wp * 8;

    extern __shared__ float sm[];
    float* ZS = sm;              // [256][65]  (z = [h, agg_h] transposed)
    float* CS = ZS + 256 * 65;   // [128][65]

    const float* hb = h + (size_t)b * NN * F_INN;

    for (int idx = tid; idx < TILE_N * F_INN; idx += NTHREADS) {
        int e = idx >> 7, k = idx & 127;
        int n = n0 + e;
        float hv = 0.f, av = 0.f;
        if (n < NN) {
            hv = hb[n * F_INN + k];
            av = g_agg_h[((size_t)b * NN + n) * HID + k];
        }
        ZS[k * 65 + e] = hv;
        ZS[(128 + k) * 65 + e] = av;
    }
    __syncthreads();

    float acc[8][4];
    gemm_tile(ZS, Wn1, 256, eb, lane, acc);       // node_mlp layer 1
    store_relu(CS, bn1, eb, lane, acc);
    __syncthreads();
    gemm_tile(CS, Wn2, HID, eb, lane, acc);       // node_mlp layer 2

    {
        float4 bb = __ldg((const float4*)bn2 + lane);
#pragma unroll
        for (int ee = 0; ee < 8; ee++) {
            int e = eb + ee;
            int n = n0 + e;
            if (n < NN) {
                float4 o;
                o.x = acc[ee][0] + bb.x + ZS[(lane * 4 + 0) * 65 + e];
                o.y = acc[ee][1] + bb.y + ZS[(lane * 4 + 1) * 65 + e];
                o.z = acc[ee][2] + bb.z + ZS[(lane * 4 + 2) * 65 + e];
                o.w = acc[ee][3] + bb.w + ZS[(lane * 4 + 3) * 65 + e];
                *(float4*)(out_h + ((size_t)b * NN + n) * F_INN + lane * 4) = o;
            }
        }
    }

    // coord epilogue: coord_new = coord + agg_c / max(cnt, 1)
    for (int idx = tid; idx < TILE_N * 12; idx += NTHREADS) {
        int e = idx / 12, c = idx % 12;
        int n = n0 + e;
        if (n < NN) {
            float cnt = fmaxf(g_cnt[n], 1.0f);
            size_t off = ((size_t)b * NN + n) * 12 + c;
            out_c[off] = coord[off] + g_agg_c[off] / cnt;
        }
    }
}

extern "C" void kernel_launch(void* const* d_in, const int* in_sizes, int n_in,
                              void* d_out, int out_size) {
    const float* h     = (const float*)d_in[0];
    const float* coord = (const float*)d_in[1];
    const int*   ei    = (const int*)  d_in[2];
    const float* ea    = (const float*)d_in[3];
    const float* We1   = (const float*)d_in[4];
    const float* be1   = (const float*)d_in[5];
    const float* We2   = (const float*)d_in[6];
    const float* be2   = (const float*)d_in[7];
    const float* Wn1   = (const float*)d_in[8];
    const float* bn1   = (const float*)d_in[9];
    const float* Wn2   = (const float*)d_in[10];
    const float* bn2   = (const float*)d_in[11];
    const float* Wc1   = (const float*)d_in[12];
    const float* bc1   = (const float*)d_in[13];
    const float* Wc2   = (const float*)d_in[14];

    float* out_h = (float*)d_out;                       // [B,N,128]
    float* out_c = out_h + (size_t)NB * NN * F_INN;     // [B,N,4,3]

    cudaFuncSetAttribute(edge_kernel, cudaFuncAttributeMaxDynamicSharedMemorySize, EDGE_SMEM_BYTES);
    cudaFuncSetAttribute(node_kernel, cudaFuncAttributeMaxDynamicSharedMemorySize, NODE_SMEM_BYTES);

    zero_kernel<<<512, 256>>>();

    dim3 egrid(NE / TILE_E, NB);    // 2500 x 2
    edge_kernel<<<egrid, NTHREADS, EDGE_SMEM_BYTES>>>(
        h, coord, ei, ea, We1, be1, We2, be2, Wc1, bc1, Wc2);

    dim3 ngrid((NN + TILE_N - 1) / TILE_N, NB);  // 79 x 2
    node_kernel<<<ngrid, NTHREADS, NODE_SMEM_BYTES>>>(
        h, coord, Wn1, bn1, Wn2, bn2, out_h, out_c);
}

// round 5
// speedup vs baseline: 2.0027x; 2.0027x over previous
#include <cuda_runtime.h>
#include <math.h>

// Problem constants (fixed by the reference)
#define NB 2
#define NN 5000
#define NE 160000
#define F_INN 128
#define HID 128
#define ED 16
#define IN_EDGE 288   // 2*128 + 16 + 16
#define TILE_E 64
#define TILE_N 64
#define NTHREADS 256
#define STR 66        // smem row stride (floats): even -> 8B-aligned edge pairs, conflict-free

typedef unsigned long long u64;

// Scratch (allocation-free rule -> __device__ globals)
__device__ float g_agg_h[NB * NN * HID];   // 5.12 MB
__device__ float g_agg_c[NB * NN * 12];    // 480 KB
__device__ float g_cnt[NN];                // 20 KB

__device__ __forceinline__ void red_add_v4(float* p, float a, float b, float c, float d) {
    asm volatile("red.global.add.v4.f32 [%0], {%1,%2,%3,%4};"
                 :: "l"(p), "f"(a), "f"(b), "f"(c), "f"(d) : "memory");
}

// Packed fp32x2 helpers (SASS FFMA2 path — only reachable via PTX f32x2 ops)
__device__ __forceinline__ u64 pack2(float x) {
    u64 r; asm("mov.b64 %0, {%1, %1};" : "=l"(r) : "f"(x)); return r;
}
__device__ __forceinline__ void unpack2(u64 v, float& lo, float& hi) {
    asm("mov.b64 {%0, %1}, %2;" : "=f"(lo), "=f"(hi) : "l"(v));
}
__device__ __forceinline__ void ffma2(u64& d, u64 a, u64 b) {
    asm("fma.rn.f32x2 %0, %1, %2, %0;" : "+l"(d) : "l"(a), "l"(b));
}

__global__ void zero_kernel() {
    int stride = gridDim.x * blockDim.x;
    int i = blockIdx.x * blockDim.x + threadIdx.x;
    for (int idx = i; idx < NB * NN * HID; idx += stride) g_agg_h[idx] = 0.f;
    for (int idx = i; idx < NB * NN * 12;  idx += stride) g_agg_c[idx] = 0.f;
    for (int idx = i; idx < NN;            idx += stride) g_cnt[idx]   = 0.f;
}

// Register-blocked tile GEMM with packed fp32x2 FMA.
// C[64 rows][128 out] += A(smem, [K][STR] transposed) * W([K][128] global).
// Thread (warp wp, lane) owns row-pairs (eb+2p, eb+2p+1), p=0..3 (eb = wp*8),
// and outputs lane*4 .. lane*4+3. Each acc[p][j] is an fp32x2 pair over 2 rows.
__device__ __forceinline__ void gemm_tile2(const float* __restrict__ A,
                                           const float* __restrict__ W,
                                           int K, int eb, int lane,
                                           u64 acc[4][4]) {
#pragma unroll
    for (int p = 0; p < 4; p++)
#pragma unroll
        for (int j = 0; j < 4; j++) acc[p][j] = 0ull;
    const float4* W4 = (const float4*)W;
#pragma unroll 2
    for (int k = 0; k < K; k++) {
        float4 w = __ldg(&W4[k * 32 + lane]);
        u64 wx = pack2(w.x), wy = pack2(w.y), wz = pack2(w.z), ww = pack2(w.w);
        const u64* ap = (const u64*)(A + k * STR + eb);   // 8B-aligned edge pairs
#pragma unroll
        for (int p = 0; p < 4; p++) {
            u64 a = ap[p];
            ffma2(acc[p][0], a, wx);
            ffma2(acc[p][1], a, wy);
            ffma2(acc[p][2], a, wz);
            ffma2(acc[p][3], a, ww);
        }
    }
}

__device__ __forceinline__ void store_relu2(float* __restrict__ S,
                                            const float* __restrict__ bias,
                                            int eb, int lane, const u64 acc[4][4]) {
    float4 bb = __ldg((const float4*)bias + lane);
    float bj[4] = {bb.x, bb.y, bb.z, bb.w};
#pragma unroll
    for (int p = 0; p < 4; p++) {
#pragma unroll
        for (int j = 0; j < 4; j++) {
            float lo, hi; unpack2(acc[p][j], lo, hi);
            float2 v = make_float2(fmaxf(lo + bj[j], 0.f), fmaxf(hi + bj[j], 0.f));
            *(float2*)(S + (lane * 4 + j) * STR + eb + 2 * p) = v;
        }
    }
}

// SMEM (floats): XS[288][STR] | EFS[128][STR] | CDS[64][12] | NRM[64] | ROWS[64] COLS[64] (ints)
#define EDGE_SMEM_FLOATS (IN_EDGE * STR + HID * STR + TILE_E * 12 + TILE_E + TILE_E)
#define EDGE_SMEM_BYTES  (EDGE_SMEM_FLOATS * 4 + TILE_E * 4)

__global__ void __launch_bounds__(NTHREADS, 2)
edge_kernel(const float* __restrict__ h, const float* __restrict__ coord,
            const int* __restrict__ ei, const float* __restrict__ ea,
            const float* __restrict__ W1, const float* __restrict__ b1,
            const float* __restrict__ W2, const float* __restrict__ b2,
            const float* __restrict__ Wc1, const float* __restrict__ bc1,
            const float* __restrict__ Wc2) {
    const int b   = blockIdx.y;
    const int e0  = blockIdx.x * TILE_E;
    const int tid = threadIdx.x;
    const int lane = tid & 31;
    const int wp   = tid >> 5;
    const int eb   = wp * 8;

    extern __shared__ float sm[];
    float* XS  = sm;                        // [288][STR]
    float* EFS = XS + IN_EDGE * STR;        // [128][STR]
    float* CDS = EFS + HID * STR;           // [64][12]
    float* NRM = CDS + TILE_E * 12;         // [64]
    int*   ROWS = (int*)(NRM + TILE_E);
    int*   COLS = ROWS + TILE_E;

    const float* hb = h + (size_t)b * NN * F_INN;
    const float* cb = coord + (size_t)b * NN * 12;

    if (tid < TILE_E) {
        ROWS[tid] = ei[e0 + tid];
        COLS[tid] = ei[NE + e0 + tid];
    }
    __syncthreads();

    // Gather h[row] (k: 0..127) and h[col] (k: 128..255) into XS (transposed).
    // Vectorized: one LDG.128 per 4 features; warp lanes cover one edge's row.
    {
        const float4* hb4 = (const float4*)hb;
        for (int idx = tid; idx < TILE_E * 32; idx += NTHREADS) {
            int e = idx >> 5, q = idx & 31;
            float4 v = hb4[ROWS[e] * 32 + q];
            XS[(4 * q + 0) * STR + e] = v.x;
            XS[(4 * q + 1) * STR + e] = v.y;
            XS[(4 * q + 2) * STR + e] = v.z;
            XS[(4 * q + 3) * STR + e] = v.w;
        }
        for (int idx = tid; idx < TILE_E * 32; idx += NTHREADS) {
            int e = idx >> 5, q = idx & 31;
            float4 v = hb4[COLS[e] * 32 + q];
            XS[(128 + 4 * q + 0) * STR + e] = v.x;
            XS[(128 + 4 * q + 1) * STR + e] = v.y;
            XS[(128 + 4 * q + 2) * STR + e] = v.z;
            XS[(128 + 4 * q + 3) * STR + e] = v.w;
        }
    }
    // cd = coord[row] - coord[col]  ([4][3] per edge)
    for (int idx = tid; idx < TILE_E * 12; idx += NTHREADS) {
        int e = idx / 12, c = idx % 12;
        CDS[e * 12 + c] = cb[ROWS[e] * 12 + c] - cb[COLS[e] * 12 + c];
    }
    // edge_attr (k: 272..287)
    for (int idx = tid; idx < TILE_E * ED; idx += NTHREADS) {
        int e = idx >> 4, c = idx & 15;
        XS[(272 + c) * STR + e] = ea[(size_t)(e0 + e) * ED + c];
    }
    __syncthreads();

    // prod[jk] = dot(cd[j], cd[k2]) (unnormalized, k: 256..271)
    for (int idx = tid; idx < TILE_E * 16; idx += NTHREADS) {
        int e = idx >> 4, jk = idx & 15;
        int j = jk >> 2, k2 = jk & 3;
        const float* cde = CDS + e * 12;
        float p = cde[j * 3] * cde[k2 * 3] + cde[j * 3 + 1] * cde[k2 * 3 + 1] +
                  cde[j * 3 + 2] * cde[k2 * 3 + 2];
        XS[(256 + jk) * STR + e] = p;
    }
    __syncthreads();
    if (tid < TILE_E) {
        float s = 0.f;
#pragma unroll
        for (int jk = 0; jk < 16; jk++) { float p = XS[(256 + jk) * STR + tid]; s += p * p; }
        NRM[tid] = 1.0f / fmaxf(sqrtf(s), 1e-12f);
    }
    __syncthreads();
    for (int idx = tid; idx < TILE_E * 16; idx += NTHREADS) {
        int e = idx >> 4, jk = idx & 15;
        XS[(256 + jk) * STR + e] *= NRM[e];
    }
    __syncthreads();

    u64 acc[4][4];

    // edge_mlp layer 1: [64,288] @ [288,128] -> relu -> EFS
    gemm_tile2(XS, W1, IN_EDGE, eb, lane, acc);
    store_relu2(EFS, b1, eb, lane, acc);
    __syncthreads();

    // edge_mlp layer 2: [64,128] @ [128,128] -> relu -> ef (regs)
    gemm_tile2(EFS, W2, HID, eb, lane, acc);
    float eflo[4][4], efhi[4][4];
    {
        float4 bb = __ldg((const float4*)b2 + lane);
        float bj[4] = {bb.x, bb.y, bb.z, bb.w};
#pragma unroll
        for (int p = 0; p < 4; p++)
#pragma unroll
            for (int j = 0; j < 4; j++) {
                float lo, hi; unpack2(acc[p][j], lo, hi);
                eflo[p][j] = fmaxf(lo + bj[j], 0.f);
                efhi[p][j] = fmaxf(hi + bj[j], 0.f);
            }
    }
    // scatter ef into agg_h: all 32 lanes of a warp hit one node's 128
    // consecutive floats -> one coalesced 512B vector reduction per (warp, edge)
#pragma unroll
    for (int p = 0; p < 4; p++) {
        int r0 = ROWS[eb + 2 * p], r1 = ROWS[eb + 2 * p + 1];
        float* q0 = g_agg_h + ((size_t)b * NN + r0) * HID + lane * 4;
        float* q1 = g_agg_h + ((size_t)b * NN + r1) * HID + lane * 4;
        red_add_v4(q0, eflo[p][0], eflo[p][1], eflo[p][2], eflo[p][3]);
        red_add_v4(q1, efhi[p][0], efhi[p][1], efhi[p][2], efhi[p][3]);
    }
    __syncthreads();   // all GEMM2 reads of EFS done
    // overwrite EFS with ef for coord_mlp input
#pragma unroll
    for (int p = 0; p < 4; p++)
#pragma unroll
        for (int j = 0; j < 4; j++)
            *(float2*)(EFS + (lane * 4 + j) * STR + eb + 2 * p) =
                make_float2(eflo[p][j], efhi[p][j]);
    __syncthreads();

    // coord_mlp layer 1: relu(ef @ Wc1 + bc1)
    gemm_tile2(EFS, Wc1, HID, eb, lane, acc);
    __syncthreads();   // all reads of ef done before overwrite
    store_relu2(EFS, bc1, eb, lane, acc);
    __syncthreads();

    // coord_mlp layer 2: [64,128] @ [128,4]; one thread per (edge, m)
    {
        int e = tid >> 2, m = tid & 3;
        float s = 0.f;
#pragma unroll 4
        for (int j = 0; j < 128; j++) s += EFS[j * STR + e] * __ldg(&Wc2[j * 4 + m]);
        int r = ROWS[e];
        float* p = g_agg_c + ((size_t)b * NN + r) * 12 + m * 3;
        const float* cde = CDS + e * 12 + m * 3;
        atomicAdd(p + 0, cde[0] * s);
        atomicAdd(p + 1, cde[1] * s);
        atomicAdd(p + 2, cde[2] * s);
    }
    // per-node edge counts (batch-independent; count once)
    if (b == 0 && tid < TILE_E) atomicAdd(&g_cnt[ROWS[tid]], 1.0f);
}

// SMEM (floats): ZS[256][STR] | CS[128][STR]
#define NODE_SMEM_BYTES ((256 * STR + 128 * STR) * 4)

__global__ void __launch_bounds__(NTHREADS, 2)
node_kernel(const float* __restrict__ h, const float* __restrict__ coord,
            const float* __restrict__ Wn1, const float* __restrict__ bn1,
            const float* __restrict__ Wn2, const float* __restrict__ bn2,
            float* __restrict__ out_h, float* __restrict__ out_c) {
    const int b   = blockIdx.y;
    const int n0  = blockIdx.x * TILE_N;
    const int tid = threadIdx.x;
    const int lane = tid & 31;
    const int wp   = tid >> 5;
    const int eb   = wp * 8;

    extern __shared__ float sm[];
    float* ZS = sm;               // [256][STR]  (z = [h, agg_h] transposed)
    float* CS = ZS + 256 * STR;   // [128][STR]

    const float* hb = h + (size_t)b * NN * F_INN;

    for (int idx = tid; idx < TILE_N * F_INN; idx += NTHREADS) {
        int e = idx >> 7, k = idx & 127;
        int n = n0 + e;
        float hv = 0.f, av = 0.f;
        if (n < NN) {
            hv = hb[n * F_INN + k];
            av = g_agg_h[((size_t)b * NN + n) * HID + k];
        }
        ZS[k * STR + e] = hv;
        ZS[(128 + k) * STR + e] = av;
    }
    __syncthreads();

    u64 acc[4][4];
    gemm_tile2(ZS, Wn1, 256, eb, lane, acc);       // node_mlp layer 1
    store_relu2(CS, bn1, eb, lane, acc);
    __syncthreads();
    gemm_tile2(CS, Wn2, HID, eb, lane, acc);       // node_mlp layer 2

    {
        float4 bb = __ldg((const float4*)bn2 + lane);
        float bj[4] = {bb.x, bb.y, bb.z, bb.w};
#pragma unroll
        for (int p = 0; p < 4; p++) {
            int na = n0 + eb + 2 * p;
            float oa[4], ob[4];
#pragma unroll
            for (int j = 0; j < 4; j++) {
                float lo, hi; unpack2(acc[p][j], lo, hi);
                float2 res = *(float2*)(ZS + (lane * 4 + j) * STR + eb + 2 * p);
                oa[j] = lo + bj[j] + res.x;
                ob[j] = hi + bj[j] + res.y;
            }
            if (na < NN)
                *(float4*)(out_h + ((size_t)b * NN + na) * F_INN + lane * 4) =
                    make_float4(oa[0], oa[1], oa[2], oa[3]);
            if (na + 1 < NN)
                *(float4*)(out_h + ((size_t)b * NN + na + 1) * F_INN + lane * 4) =
                    make_float4(ob[0], ob[1], ob[2], ob[3]);
        }
    }

    // coord epilogue: coord_new = coord + agg_c / max(cnt, 1)
    for (int idx = tid; idx < TILE_N * 12; idx += NTHREADS) {
        int e = idx / 12, c = idx % 12;
        int n = n0 + e;
        if (n < NN) {
            float cnt = fmaxf(g_cnt[n], 1.0f);
            size_t off = ((size_t)b * NN + n) * 12 + c;
            out_c[off] = coord[off] + g_agg_c[off] / cnt;
        }
    }
}

extern "C" void kernel_launch(void* const* d_in, const int* in_sizes, int n_in,
                              void* d_out, int out_size) {
    const float* h     = (const float*)d_in[0];
    const float* coord = (const float*)d_in[1];
    const int*   ei    = (const int*)  d_in[2];
    const float* ea    = (const float*)d_in[3];
    const float* We1   = (const float*)d_in[4];
    const float* be1   = (const float*)d_in[5];
    const float* We2   = (const float*)d_in[6];
    const float* be2   = (const float*)d_in[7];
    const float* Wn1   = (const float*)d_in[8];
    const float* bn1   = (const float*)d_in[9];
    const float* Wn2   = (const float*)d_in[10];
    const float* bn2   = (const float*)d_in[11];
    const float* Wc1   = (const float*)d_in[12];
    const float* bc1   = (const float*)d_in[13];
    const float* Wc2   = (const float*)d_in[14];

    float* out_h = (float*)d_out;                       // [B,N,128]
    float* out_c = out_h + (size_t)NB * NN * F_INN;     // [B,N,4,3]

    cudaFuncSetAttribute(edge_kernel, cudaFuncAttributeMaxDynamicSharedMemorySize, EDGE_SMEM_BYTES);
    cudaFuncSetAttribute(node_kernel, cudaFuncAttributeMaxDynamicSharedMemorySize, NODE_SMEM_BYTES);

    zero_kernel<<<512, 256>>>();

    dim3 egrid(NE / TILE_E, NB);    // 2500 x 2
    edge_kernel<<<egrid, NTHREADS, EDGE_SMEM_BYTES>>>(
        h, coord, ei, ea, We1, be1, We2, be2, Wc1, bc1, Wc2);

    dim3 ngrid((NN + TILE_N - 1) / TILE_N, NB);  // 79 x 2
    node_kernel<<<ngrid, NTHREADS, NODE_SMEM_BYTES>>>(
        h, coord, Wn1, bn1, Wn2, bn2, out_h, out_c);
}

// round 7
// speedup vs baseline: 2.8118x; 1.4040x over previous
#include <cuda_runtime.h>
#include <math.h>

// Problem constants (fixed by the reference)
#define NB 2
#define NN 5000
#define NE 160000
#define F_INN 128
#define HID 128
#define ED 16
#define IN_EDGE 288   // 2*128 + 16 + 16
#define TILE_E 64
#define TILE_N 64
#define NTHREADS 256
#define STR 66        // smem row stride (floats): even -> 8B-aligned edge pairs, conflict-free

typedef unsigned long long u64;

// Scratch (allocation-free rule -> __device__ globals)
__device__ float g_agg_h[NB * NN * HID];   // 5.12 MB
__device__ float g_agg_c[NB * NN * 12];    // 480 KB
__device__ float g_cnt[NN];                // 20 KB

__device__ __forceinline__ void red_add_v4(float* p, float a, float b, float c, float d) {
    asm volatile("red.global.add.v4.f32 [%0], {%1,%2,%3,%4};"
                 :: "l"(p), "f"(a), "f"(b), "f"(c), "f"(d) : "memory");
}

// Packed fp32x2 helpers (SASS FFMA2 path — only reachable via PTX f32x2 ops)
__device__ __forceinline__ u64 pack2(float x) {
    u64 r; asm("mov.b64 %0, {%1, %1};" : "=l"(r) : "f"(x)); return r;
}
__device__ __forceinline__ void unpack2(u64 v, float& lo, float& hi) {
    asm("mov.b64 {%0, %1}, %2;" : "=f"(lo), "=f"(hi) : "l"(v));
}
__device__ __forceinline__ void ffma2(u64& d, u64 a, u64 b) {
    asm("fma.rn.f32x2 %0, %1, %2, %0;" : "+l"(d) : "l"(a), "l"(b));
}

__global__ void zero_kernel() {
    int stride = gridDim.x * blockDim.x;
    int i = blockIdx.x * blockDim.x + threadIdx.x;
    for (int idx = i; idx < NB * NN * HID; idx += stride) g_agg_h[idx] = 0.f;
    for (int idx = i; idx < NB * NN * 12;  idx += stride) g_agg_c[idx] = 0.f;
    for (int idx = i; idx < NN;            idx += stride) g_cnt[idx]   = 0.f;
}

// Register-blocked tile GEMM with packed fp32x2 FMA and software-pipelined
// (register double-buffered) W prefetch. L1D carveout is ~0 (smem-maxed SM),
// so W loads are L2 hits (~234 cyc) — chunking K by 4 keeps 4 LDG.128 in
// flight while 64 FFMA2 execute, hiding the L2 latency.
// C[64 rows][128 out] += A(smem, [K][STR] transposed) * W([K][128] global).
// Thread (warp wp, lane) owns row-pairs (eb+2p, eb+2p+1), p=0..3 (eb = wp*8),
// and outputs lane*4 .. lane*4+3. Each acc[p][j] is an fp32x2 pair over 2 rows.
__device__ __forceinline__ void gemm_tile2(const float* __restrict__ A,
                                           const float* __restrict__ W,
                                           int K, int eb, int lane,
                                           u64 acc[4][4]) {
#pragma unroll
    for (int p = 0; p < 4; p++)
#pragma unroll
        for (int j = 0; j < 4; j++) acc[p][j] = 0ull;
    const float4* W4 = (const float4*)W;

    float4 wbuf[4];
#pragma unroll
    for (int i = 0; i < 4; i++) wbuf[i] = __ldg(&W4[i * 32 + lane]);

    for (int k0 = 0; k0 < K; k0 += 4) {
        float4 wn[4];
#pragma unroll
        for (int i = 0; i < 4; i++) wn[i] = wbuf[i];
        if (k0 + 4 < K) {
#pragma unroll
            for (int i = 0; i < 4; i++) wn[i] = __ldg(&W4[(k0 + 4 + i) * 32 + lane]);
        }
#pragma unroll
        for (int i = 0; i < 4; i++) {
            u64 wx = pack2(wbuf[i].x), wy = pack2(wbuf[i].y),
                wz = pack2(wbuf[i].z), ww = pack2(wbuf[i].w);
            const u64* ap = (const u64*)(A + (k0 + i) * STR + eb);
#pragma unroll
            for (int p = 0; p < 4; p++) {
                u64 a = ap[p];
                ffma2(acc[p][0], a, wx);
                ffma2(acc[p][1], a, wy);
                ffma2(acc[p][2], a, wz);
                ffma2(acc[p][3], a, ww);
            }
        }
#pragma unroll
        for (int i = 0; i < 4; i++) wbuf[i] = wn[i];
    }
}

__device__ __forceinline__ void store_relu2(float* __restrict__ S,
                                            const float* __restrict__ bias,
                                            int eb, int lane, const u64 acc[4][4]) {
    float4 bb = __ldg((const float4*)bias + lane);
    float bj[4] = {bb.x, bb.y, bb.z, bb.w};
#pragma unroll
    for (int p = 0; p < 4; p++) {
#pragma unroll
        for (int j = 0; j < 4; j++) {
            float lo, hi; unpack2(acc[p][j], lo, hi);
            float2 v = make_float2(fmaxf(lo + bj[j], 0.f), fmaxf(hi + bj[j], 0.f));
            *(float2*)(S + (lane * 4 + j) * STR + eb + 2 * p) = v;
        }
    }
}

// SMEM (floats): XS[288][STR] | EFS[128][STR] | CDS[64][12] | NRM[64] | ROWS[64] COLS[64] (ints)
#define EDGE_SMEM_FLOATS (IN_EDGE * STR + HID * STR + TILE_E * 12 + TILE_E + TILE_E)
#define EDGE_SMEM_BYTES  (EDGE_SMEM_FLOATS * 4 + TILE_E * 4)

__global__ void __launch_bounds__(NTHREADS, 2)
edge_kernel(const float* __restrict__ h, const float* __restrict__ coord,
            const int* __restrict__ ei, const float* __restrict__ ea,
            const float* __restrict__ W1, const float* __restrict__ b1,
            const float* __restrict__ W2, const float* __restrict__ b2,
            const float* __restrict__ Wc1, const float* __restrict__ bc1,
            const float* __restrict__ Wc2) {
    const int b   = blockIdx.y;
    const int e0  = blockIdx.x * TILE_E;
    const int tid = threadIdx.x;
    const int lane = tid & 31;
    const int wp   = tid >> 5;
    const int eb   = wp * 8;

    extern __shared__ float sm[];
    float* XS  = sm;                        // [288][STR]
    float* EFS = XS + IN_EDGE * STR;        // [128][STR]
    float* CDS = EFS + HID * STR;           // [64][12]
    float* NRM = CDS + TILE_E * 12;         // [64]
    int*   ROWS = (int*)(NRM + TILE_E);
    int*   COLS = ROWS + TILE_E;

    const float* hb = h + (size_t)b * NN * F_INN;
    const float* cb = coord + (size_t)b * NN * 12;

    if (tid < TILE_E) {
        ROWS[tid] = ei[e0 + tid];
        COLS[tid] = ei[NE + e0 + tid];
    }
    __syncthreads();

    // Gather h[row] (k: 0..127) and h[col] (k: 128..255) into XS (transposed).
    // Vectorized: one LDG.128 per 4 features; warp lanes cover one edge's row.
    {
        const float4* hb4 = (const float4*)hb;
        for (int idx = tid; idx < TILE_E * 32; idx += NTHREADS) {
            int e = idx >> 5, q = idx & 31;
            float4 v = hb4[ROWS[e] * 32 + q];
            XS[(4 * q + 0) * STR + e] = v.x;
            XS[(4 * q + 1) * STR + e] = v.y;
            XS[(4 * q + 2) * STR + e] = v.z;
            XS[(4 * q + 3) * STR + e] = v.w;
        }
        for (int idx = tid; idx < TILE_E * 32; idx += NTHREADS) {
            int e = idx >> 5, q = idx & 31;
            float4 v = hb4[COLS[e] * 32 + q];
            XS[(128 + 4 * q + 0) * STR + e] = v.x;
            XS[(128 + 4 * q + 1) * STR + e] = v.y;
            XS[(128 + 4 * q + 2) * STR + e] = v.z;
            XS[(128 + 4 * q + 3) * STR + e] = v.w;
        }
    }
    // cd = coord[row] - coord[col]  ([4][3] per edge)
    for (int idx = tid; idx < TILE_E * 12; idx += NTHREADS) {
        int e = idx / 12, c = idx % 12;
        CDS[e * 12 + c] = cb[ROWS[e] * 12 + c] - cb[COLS[e] * 12 + c];
    }
    // edge_attr (k: 272..287)
    for (int idx = tid; idx < TILE_E * ED; idx += NTHREADS) {
        int e = idx >> 4, c = idx & 15;
        XS[(272 + c) * STR + e] = ea[(size_t)(e0 + e) * ED + c];
    }
    __syncthreads();

    // prod[jk] = dot(cd[j], cd[k2]) (unnormalized, k: 256..271)
    for (int idx = tid; idx < TILE_E * 16; idx += NTHREADS) {
        int e = idx >> 4, jk = idx & 15;
        int j = jk >> 2, k2 = jk & 3;
        const float* cde = CDS + e * 12;
        float p = cde[j * 3] * cde[k2 * 3] + cde[j * 3 + 1] * cde[k2 * 3 + 1] +
                  cde[j * 3 + 2] * cde[k2 * 3 + 2];
        XS[(256 + jk) * STR + e] = p;
    }
    __syncthreads();
    if (tid < TILE_E) {
        float s = 0.f;
#pragma unroll
        for (int jk = 0; jk < 16; jk++) { float p = XS[(256 + jk) * STR + tid]; s += p * p; }
        NRM[tid] = 1.0f / fmaxf(sqrtf(s), 1e-12f);
    }
    __syncthreads();
    for (int idx = tid; idx < TILE_E * 16; idx += NTHREADS) {
        int e = idx >> 4, jk = idx & 15;
        XS[(256 + jk) * STR + e] *= NRM[e];
    }
    __syncthreads();

    u64 acc[4][4];

    // edge_mlp layer 1: [64,288] @ [288,128] -> relu -> EFS
    gemm_tile2(XS, W1, IN_EDGE, eb, lane, acc);
    store_relu2(EFS, b1, eb, lane, acc);
    __syncthreads();

    // edge_mlp layer 2: [64,128] @ [128,128] -> relu -> ef (regs)
    gemm_tile2(EFS, W2, HID, eb, lane, acc);
    float eflo[4][4], efhi[4][4];
    {
        float4 bb = __ldg((const float4*)b2 + lane);
        float bj[4] = {bb.x, bb.y, bb.z, bb.w};
#pragma unroll
        for (int p = 0; p < 4; p++)
#pragma unroll
            for (int j = 0; j < 4; j++) {
                float lo, hi; unpack2(acc[p][j], lo, hi);
                eflo[p][j] = fmaxf(lo + bj[j], 0.f);
                efhi[p][j] = fmaxf(hi + bj[j], 0.f);
            }
    }
    // scatter ef into agg_h: all 32 lanes of a warp hit one node's 128
    // consecutive floats -> one coalesced 512B vector reduction per (warp, edge)
#pragma unroll
    for (int p = 0; p < 4; p++) {
        int r0 = ROWS[eb + 2 * p], r1 = ROWS[eb + 2 * p + 1];
        float* q0 = g_agg_h + ((size_t)b * NN + r0) * HID + lane * 4;
        float* q1 = g_agg_h + ((size_t)b * NN + r1) * HID + lane * 4;
        red_add_v4(q0, eflo[p][0], eflo[p][1], eflo[p][2], eflo[p][3]);
        red_add_v4(q1, efhi[p][0], efhi[p][1], efhi[p][2], efhi[p][3]);
    }
    __syncthreads();   // all GEMM2 reads of EFS done
    // overwrite EFS with ef for coord_mlp input
#pragma unroll
    for (int p = 0; p < 4; p++)
#pragma unroll
        for (int j = 0; j < 4; j++)
            *(float2*)(EFS + (lane * 4 + j) * STR + eb + 2 * p) =
                make_float2(eflo[p][j], efhi[p][j]);
    __syncthreads();

    // coord_mlp layer 1: relu(ef @ Wc1 + bc1)
    gemm_tile2(EFS, Wc1, HID, eb, lane, acc);
    __syncthreads();   // all reads of ef done before overwrite
    store_relu2(EFS, bc1, eb, lane, acc);
    __syncthreads();

    // coord_mlp layer 2: [64,128] @ [128,4]; one thread per (edge, m)
    {
        int e = tid >> 2, m = tid & 3;
        float s = 0.f;
#pragma unroll 4
        for (int j = 0; j < 128; j++) s += EFS[j * STR + e] * __ldg(&Wc2[j * 4 + m]);
        int r = ROWS[e];
        float* p = g_agg_c + ((size_t)b * NN + r) * 12 + m * 3;
        const float* cde = CDS + e * 12 + m * 3;
        atomicAdd(p + 0, cde[0] * s);
        atomicAdd(p + 1, cde[1] * s);
        atomicAdd(p + 2, cde[2] * s);
    }
    // per-node edge counts (batch-independent; count once)
    if (b == 0 && tid < TILE_E) atomicAdd(&g_cnt[ROWS[tid]], 1.0f);
}

// SMEM (floats): ZS[256][STR] | CS[128][STR]
#define NODE_SMEM_BYTES ((256 * STR + 128 * STR) * 4)

__global__ void __launch_bounds__(NTHREADS, 2)
node_kernel(const float* __restrict__ h, const float* __restrict__ coord,
            const float* __restrict__ Wn1, const float* __restrict__ bn1,
            const float* __restrict__ Wn2, const float* __restrict__ bn2,
            float* __restrict__ out_h, float* __restrict__ out_c) {
    const int b   = blockIdx.y;
    const int n0  = blockIdx.x * TILE_N;
    const int tid = threadIdx.x;
    const int lane = tid & 31;
    const int wp   = tid >> 5;
    const int eb   = wp * 8;

    extern __shared__ float sm[];
    float* ZS = sm;               // [256][STR]  (z = [h, agg_h] transposed)
    float* CS = ZS + 256 * STR;   // [128][STR]

    const float* hb = h + (size_t)b * NN * F_INN;

    for (int idx = tid; idx < TILE_N * F_INN; idx += NTHREADS) {
        int e = idx >> 7, k = idx & 127;
        int n = n0 + e;
        float hv = 0.f, av = 0.f;
        if (n < NN) {
            hv = hb[n * F_INN + k];
            av = g_agg_h[((size_t)b * NN + n) * HID + k];
        }
        ZS[k * STR + e] = hv;
        ZS[(128 + k) * STR + e] = av;
    }
    __syncthreads();

    u64 acc[4][4];
    gemm_tile2(ZS, Wn1, 256, eb, lane, acc);       // node_mlp layer 1
    store_relu2(CS, bn1, eb, lane, acc);
    __syncthreads();
    gemm_tile2(CS, Wn2, HID, eb, lane, acc);       // node_mlp layer 2

    {
        float4 bb = __ldg((const float4*)bn2 + lane);
        float bj[4] = {bb.x, bb.y, bb.z, bb.w};
#pragma unroll
        for (int p = 0; p < 4; p++) {
            int na = n0 + eb + 2 * p;
            float oa[4], ob[4];
#pragma unroll
            for (int j = 0; j < 4; j++) {
                float lo, hi; unpack2(acc[p][j], lo, hi);
                float2 res = *(float2*)(ZS + (lane * 4 + j) * STR + eb + 2 * p);
                oa[j] = lo + bj[j] + res.x;
                ob[j] = hi + bj[j] + res.y;
            }
            if (na < NN)
                *(float4*)(out_h + ((size_t)b * NN + na) * F_INN + lane * 4) =
                    make_float4(oa[0], oa[1], oa[2], oa[3]);
            if (na + 1 < NN)
                *(float4*)(out_h + ((size_t)b * NN + na + 1) * F_INN + lane * 4) =
                    make_float4(ob[0], ob[1], ob[2], ob[3]);
        }
    }

    // coord epilogue: coord_new = coord + agg_c / max(cnt, 1)
    for (int idx = tid; idx < TILE_N * 12; idx += NTHREADS) {
        int e = idx / 12, c = idx % 12;
        int n = n0 + e;
        if (n < NN) {
            float cnt = fmaxf(g_cnt[n], 1.0f);
            size_t off = ((size_t)b * NN + n) * 12 + c;
            out_c[off] = coord[off] + g_agg_c[off] / cnt;
        }
    }
}

extern "C" void kernel_launch(void* const* d_in, const int* in_sizes, int n_in,
                              void* d_out, int out_size) {
    const float* h     = (const float*)d_in[0];
    const float* coord = (const float*)d_in[1];
    const int*   ei    = (const int*)  d_in[2];
    const float* ea    = (const float*)d_in[3];
    const float* We1   = (const float*)d_in[4];
    const float* be1   = (const float*)d_in[5];
    const float* We2   = (const float*)d_in[6];
    const float* be2   = (const float*)d_in[7];
    const float* Wn1   = (const float*)d_in[8];
    const float* bn1   = (const float*)d_in[9];
    const float* Wn2   = (const float*)d_in[10];
    const float* bn2   = (const float*)d_in[11];
    const float* Wc1   = (const float*)d_in[12];
    const float* bc1   = (const float*)d_in[13];
    const float* Wc2   = (const float*)d_in[14];

    float* out_h = (float*)d_out;                       // [B,N,128]
    float* out_c = out_h + (size_t)NB * NN * F_INN;     // [B,N,4,3]

    cudaFuncSetAttribute(edge_kernel, cudaFuncAttributeMaxDynamicSharedMemorySize, EDGE_SMEM_BYTES);
    cudaFuncSetAttribute(node_kernel, cudaFuncAttributeMaxDynamicSharedMemorySize, NODE_SMEM_BYTES);

    zero_kernel<<<512, 256>>>();

    dim3 egrid(NE / TILE_E, NB);    // 2500 x 2
    edge_kernel<<<egrid, NTHREADS, EDGE_SMEM_BYTES>>>(
        h, coord, ei, ea, We1, be1, We2, be2, Wc1, bc1, Wc2);

    dim3 ngrid((NN + TILE_N - 1) / TILE_N, NB);  // 79 x 2
    node_kernel<<<ngrid, NTHREADS, NODE_SMEM_BYTES>>>(
        h, coord, Wn1, bn1, Wn2, bn2, out_h, out_c);
}